// round 10
// baseline (speedup 1.0000x reference)
#include <cuda_runtime.h>
#include <cstdint>
#include <math.h>

#define H 2048
#define L 350

// -------- persistent scratch (no allocs allowed) --------
__device__ float g_logits[L];              // attn logits (pre-bias)
// unified scratch: [0,2048) x copy | [2048,4096) ctx (atomic, zeroed each replay) |
// [4096,6144) gsum | [6144,12288) gi | [12288,18432) gh
#define SC_VEC   0
#define SC_GSUM  4096
#define SC_GI    6144
#define SC_GH    12288
#define SC_TOTAL 18432
__device__ __align__(16) float g_scr[SC_TOTAL];
__device__ int g_done;                     // kE completion counter (self-resetting)

__device__ __forceinline__ float warp_sum(float v) {
    #pragma unroll
    for (int o = 16; o > 0; o >>= 1) v += __shfl_xor_sync(0xffffffffu, v, o);
    return v;
}
__device__ __forceinline__ float dot4(float4 a, float4 b) {
    return a.x*b.x + a.y*b.y + a.z*b.z + a.w*b.w;
}

// One 2048-col row dot: burst 16 LDG.128 (8 KB/warp in flight), then dot
// against an smem-staged vector. Caller does warp_sum.
__device__ __forceinline__ float row_dot16(
    const float4* __restrict__ W, const float4* sv, int lane)
{
    float4 w[16];
    #pragma unroll
    for (int u = 0; u < 16; u++) w[u] = __ldcs(&W[lane + 32*u]);
    float s = 0.f;
    #pragma unroll
    for (int u = 0; u < 16; u++) s += dot4(w[u], sv[lane + 32*u]);
    return s;
}

// ============================================================
// kA: blocks [0,44)   attn logits, warp-per-row (stage [x;h] 16 KB)
//     blocks [44,284) w_hh rows 0..1919, warp-per-row (stage h 8 KB)
//     block  284      zero ctx + copy x -> g_scr[SC_VEC]
// ============================================================
#define KA_BLOCKS 285
__global__ __launch_bounds__(256) void kA(
    const float* __restrict__ x, const float* __restrict__ h,
    const float* __restrict__ attn_W, const float* __restrict__ w_hh)
{
    __shared__ __align__(16) float4 sv[1024];
    int tid  = threadIdx.x;
    int lane = tid & 31;
    int wid  = tid >> 5;

    if (blockIdx.x < 44) {
        const float4* x4 = (const float4*)x;
        const float4* h4 = (const float4*)h;
        #pragma unroll
        for (int i = tid; i < 512; i += 256) { sv[i] = x4[i]; sv[512 + i] = h4[i]; }
        __syncthreads();
        int row = blockIdx.x * 8 + wid;
        if (row < L) {
            const float4* W = (const float4*)(attn_W + (size_t)row * 2 * H);
            float s = row_dot16(W, sv, lane) + row_dot16(W + 512, sv + 512, lane);
            s = warp_sum(s);
            if (lane == 0) g_logits[row] = s;
        }
    } else if (blockIdx.x < 284) {
        const float4* h4 = (const float4*)h;
        #pragma unroll
        for (int i = tid; i < 512; i += 256) sv[i] = h4[i];
        __syncthreads();
        int r = (blockIdx.x - 44) * 8 + wid;          // 0..1919
        const float4* W = (const float4*)(w_hh + (size_t)r * H);
        float s = row_dot16(W, sv, lane);
        s = warp_sum(s);
        if (lane == 0) g_scr[SC_GH + r] = s;
    } else {
        // zero ctx [2048,4096), copy x -> [0,2048)
        float4* ctx4 = (float4*)(g_scr + 2048);
        float4* vec4 = (float4*)(g_scr + SC_VEC);
        const float4* x4 = (const float4*)x;
        ctx4[tid]       = make_float4(0.f, 0.f, 0.f, 0.f);
        ctx4[tid + 256] = make_float4(0.f, 0.f, 0.f, 0.f);
        vec4[tid]       = x4[tid];
        vec4[tid + 256] = x4[tid + 256];
    }
}

// ============================================================
// kBC: blocks [0,112)  softmax (redundant, L2-hot) + ctx partial
//        decode: bx = b & 7 (256-col chunk), by = b >> 3 (25-row chunk)
//      blocks [112,352) w_hh rows 1920..3839
// ============================================================
#define KBC_BLOCKS 352
__global__ __launch_bounds__(256) void kBC(
    const float* __restrict__ h, const float* __restrict__ attn_b,
    const float* __restrict__ enc, const float* __restrict__ w_hh,
    float* __restrict__ out)
{
    __shared__ __align__(16) float4 svv[512];
    __shared__ float sw[L];
    __shared__ float red[256];
    int tid = threadIdx.x;

    if (blockIdx.x < 112) {
        float m = -INFINITY;
        for (int i = tid; i < L; i += 256) {
            float v = g_logits[i] + attn_b[i];
            sw[i] = v; m = fmaxf(m, v);
        }
        red[tid] = m; __syncthreads();
        #pragma unroll
        for (int s = 128; s > 0; s >>= 1) { if (tid < s) red[tid] = fmaxf(red[tid], red[tid+s]); __syncthreads(); }
        float mx = red[0]; __syncthreads();

        float sum = 0.f;
        for (int i = tid; i < L; i += 256) { float e = __expf(sw[i] - mx); sw[i] = e; sum += e; }
        red[tid] = sum; __syncthreads();
        #pragma unroll
        for (int s = 128; s > 0; s >>= 1) { if (tid < s) red[tid] += red[tid+s]; __syncthreads(); }
        float inv = 1.f / red[0]; __syncthreads();
        for (int i = tid; i < L; i += 256) sw[i] *= inv;
        __syncthreads();

        if (blockIdx.x == 0)
            for (int i = tid; i < L; i += 256) out[2*H + i] = sw[i];

        int bx = blockIdx.x & 7, by = blockIdx.x >> 3;
        int j  = bx * 256 + tid;
        int r0 = by * 25;
        const float* e = enc + (size_t)r0 * H + j;
        float acc = 0.f;
        #pragma unroll
        for (int i = 0; i < 25; ++i)
            acc += sw[r0 + i] * e[(size_t)i * H];
        atomicAdd(&g_scr[SC_VEC + 2048 + j], acc);
    } else {
        int lane = tid & 31, wid = tid >> 5;
        const float4* h4 = (const float4*)h;
        #pragma unroll
        for (int i = tid; i < 512; i += 256) svv[i] = h4[i];
        __syncthreads();
        int r = 1920 + (blockIdx.x - 112) * 8 + wid;  // 1920..3839
        const float4* W = (const float4*)(w_hh + (size_t)r * H);
        float s = row_dot16(W, svv, lane);
        s = warp_sum(s);
        if (lane == 0) g_scr[SC_GH + r] = s;
    }
}

// ============================================================
// kD: blocks [0,256)   comb_W @ [x;ctx], warp-per-row (stage 16 KB)
//     blocks [256,544) w_hh rows 3840..6143 (stage h 8 KB)
// ============================================================
#define KD_BLOCKS 544
__global__ __launch_bounds__(256) void kD(
    const float* __restrict__ h,
    const float* __restrict__ comb_W, const float* __restrict__ w_hh)
{
    __shared__ __align__(16) float4 sv[1024];
    int tid  = threadIdx.x;
    int lane = tid & 31;
    int wid  = tid >> 5;

    if (blockIdx.x < 256) {
        const float4* gv = (const float4*)(g_scr + SC_VEC);
        #pragma unroll
        for (int i = tid; i < 1024; i += 256) sv[i] = gv[i];
        __syncthreads();
        int row = blockIdx.x * 8 + wid;
        const float4* W = (const float4*)(comb_W + (size_t)row * 2 * H);
        float s = row_dot16(W, sv, lane) + row_dot16(W + 512, sv + 512, lane);
        s = warp_sum(s);
        if (lane == 0) g_scr[SC_GSUM + row] = s;
    } else {
        const float4* h4 = (const float4*)h;
        #pragma unroll
        for (int i = tid; i < 512; i += 256) sv[i] = h4[i];
        __syncthreads();
        int r = 3840 + (blockIdx.x - 256) * 8 + wid;  // 3840..6143
        const float4* W = (const float4*)(w_hh + (size_t)r * H);
        float s = row_dot16(W, sv, lane);
        s = warp_sum(s);
        if (lane == 0) g_scr[SC_GH + r] = s;
    }
}

// ============================================================
// kE: gi = w_ih @ relu(gsum + comb_b), warp-per-row, 768 blocks.
// Last block to finish runs the GRU gate epilogue (threadfence pattern).
// ============================================================
#define KE_BLOCKS 768
__global__ __launch_bounds__(256) void kE(
    const float* __restrict__ w_ih, const float* __restrict__ comb_b,
    const float* __restrict__ h, const float* __restrict__ b_ih,
    const float* __restrict__ b_hh, float* __restrict__ out)
{
    __shared__ __align__(16) float4 sv[512];
    __shared__ int is_last;
    int tid  = threadIdx.x;
    int lane = tid & 31;
    int wid  = tid >> 5;

    const float4* gs = (const float4*)(g_scr + SC_GSUM);
    const float4* cb = (const float4*)comb_b;
    #pragma unroll
    for (int i = tid; i < 512; i += 256) {
        float4 gv = gs[i], bv = cb[i];
        sv[i] = make_float4(fmaxf(gv.x + bv.x, 0.f), fmaxf(gv.y + bv.y, 0.f),
                            fmaxf(gv.z + bv.z, 0.f), fmaxf(gv.w + bv.w, 0.f));
    }
    __syncthreads();

    int row = blockIdx.x * 8 + wid;
    const float4* W = (const float4*)(w_ih + (size_t)row * H);
    float s = row_dot16(W, sv, lane);
    s = warp_sum(s);
    if (lane == 0) g_scr[SC_GI + row] = s;

    // last-block epilogue
    __syncthreads();
    if (tid == 0) {
        __threadfence();
        int old = atomicAdd(&g_done, 1);
        is_last = (old == KE_BLOCKS - 1);
    }
    __syncthreads();
    if (is_last) {
        if (tid == 0) g_done = 0;      // reset for next graph replay
        __threadfence();
        for (int j = tid; j < H; j += 256) {
            float hr = g_scr[SC_GH + j]       + b_hh[j];
            float hz = g_scr[SC_GH + j + H]   + b_hh[j + H];
            float hn = g_scr[SC_GH + j + 2*H] + b_hh[j + 2*H];
            float ir = g_scr[SC_GI + j]       + b_ih[j]       + hr;
            float iz = g_scr[SC_GI + j + H]   + b_ih[j + H]   + hz;
            float r  = 1.f / (1.f + __expf(-ir));
            float z  = 1.f / (1.f + __expf(-iz));
            float n  = tanhf(g_scr[SC_GI + j + 2*H] + b_ih[j + 2*H] + r * hn);
            float hv = (1.f - z) * n + z * h[j];
            out[j]     = hv;
            out[H + j] = hv;
        }
    }
}

// ============================================================
extern "C" void kernel_launch(void* const* d_in, const int* in_sizes, int n_in,
                              void* d_out, int out_size)
{
    const float* x      = (const float*)d_in[0];
    const float* h      = (const float*)d_in[1];
    const float* enc    = (const float*)d_in[2];
    const float* attn_W = (const float*)d_in[3];
    const float* attn_b = (const float*)d_in[4];
    const float* comb_W = (const float*)d_in[5];
    const float* comb_b = (const float*)d_in[6];
    const float* w_ih   = (const float*)d_in[7];
    const float* w_hh   = (const float*)d_in[8];
    const float* b_ih   = (const float*)d_in[9];
    const float* b_hh   = (const float*)d_in[10];
    float* out = (float*)d_out;

    kA<<<KA_BLOCKS, 256>>>(x, h, attn_W, w_hh);
    kBC<<<KBC_BLOCKS, 256>>>(h, attn_b, enc, w_hh, out);
    kD<<<KD_BLOCKS, 256>>>(h, comb_W, w_hh);
    kE<<<KE_BLOCKS, 256>>>(w_ih, comb_b, h, b_ih, b_hh, out);
}

// round 11
// speedup vs baseline: 1.1429x; 1.1429x over previous
#include <cuda_runtime.h>
#include <cstdint>
#include <math.h>

#define H 2048
#define L 350

// -------- persistent scratch (no allocs allowed) --------
__device__ float g_logits[L];              // attn logits (pre-bias)
// unified scratch: [0,2048) x copy | [2048,4096) ctx (atomic, zeroed each replay) |
// [4096,6144) gsum | [6144,12288) gi | [12288,18432) gh
#define SC_VEC   0
#define SC_GSUM  4096
#define SC_GI    6144
#define SC_GH    12288
#define SC_TOTAL 18432
__device__ __align__(16) float g_scr[SC_TOTAL];
__device__ int g_done;                     // kE completion counter (self-resetting)

__device__ __forceinline__ float warp_sum(float v) {
    #pragma unroll
    for (int o = 16; o > 0; o >>= 1) v += __shfl_xor_sync(0xffffffffu, v, o);
    return v;
}
__device__ __forceinline__ float dot4(float4 a, float4 b) {
    return a.x*b.x + a.y*b.y + a.z*b.z + a.w*b.w;
}

// Burst-8 segment dot: 8 LDG.128 front-batched (32 regs — ptxas keeps this
// resident; 16 does NOT), then 8 smem dots. 256 float4 segment per warp.
__device__ __forceinline__ float seg_dot8(
    const float4* __restrict__ W, const float4* sv, int lane)
{
    float4 w[8];
    #pragma unroll
    for (int u = 0; u < 8; u++) w[u] = __ldcs(&W[lane + 32*u]);
    float s = 0.f;
    #pragma unroll
    for (int u = 0; u < 8; u++) s += dot4(w[u], sv[lane + 32*u]);
    return s;
}

// ============================================================
// kA: blocks [0,175)    attn logits (2 rows/block, warp per quarter)
//     blocks [175,655)  w_hh rows 0..1919 (4 rows/block, warp per half)
//     block  655        zero ctx + copy x -> g_scr[SC_VEC]
// ============================================================
#define KA_BLOCKS 656
__global__ __launch_bounds__(256) void kA(
    const float* __restrict__ x, const float* __restrict__ h,
    const float* __restrict__ attn_W, const float* __restrict__ w_hh)
{
    __shared__ __align__(16) float4 sv[1024];
    __shared__ float pr[8];
    int tid  = threadIdx.x;
    int lane = tid & 31;
    int wid  = tid >> 5;
    const float4* x4 = (const float4*)x;
    const float4* h4 = (const float4*)h;

    if (blockIdx.x < 175) {
        #pragma unroll
        for (int i = tid; i < 512; i += 256) { sv[i] = x4[i]; sv[512 + i] = h4[i]; }
        __syncthreads();
        int row = blockIdx.x * 2 + (wid >> 2);    // 350 = 175*2 exact
        int q   = wid & 3;
        const float4* W = (const float4*)(attn_W + (size_t)row * 2 * H) + q * 256;
        float s = seg_dot8(W, sv + q * 256, lane);
        s = warp_sum(s);
        if (lane == 0) pr[wid] = s;
        __syncthreads();
        if (tid < 2)
            g_logits[blockIdx.x * 2 + tid] =
                pr[tid*4] + pr[tid*4+1] + pr[tid*4+2] + pr[tid*4+3];
    } else if (blockIdx.x < 655) {
        #pragma unroll
        for (int i = tid; i < 512; i += 256) sv[i] = h4[i];
        __syncthreads();
        int b   = blockIdx.x - 175;               // 0..479
        int row = b * 4 + (wid >> 1);             // rows 0..1919
        int hf  = wid & 1;
        const float4* W = (const float4*)w_hh + (size_t)row * 512 + hf * 256;
        float s = seg_dot8(W, sv + hf * 256, lane);
        s = warp_sum(s);
        if (lane == 0) pr[wid] = s;
        __syncthreads();
        if (tid < 4) g_scr[SC_GH + b * 4 + tid] = pr[tid*2] + pr[tid*2+1];
    } else {
        float4* ctx4 = (float4*)(g_scr + 2048);
        float4* vec4 = (float4*)(g_scr + SC_VEC);
        ctx4[tid]       = make_float4(0.f, 0.f, 0.f, 0.f);
        ctx4[tid + 256] = make_float4(0.f, 0.f, 0.f, 0.f);
        vec4[tid]       = x4[tid];
        vec4[tid + 256] = x4[tid + 256];
    }
}

// ============================================================
// kBC: blocks [0,112)   softmax (redundant, L2-hot) + ctx partial
//      blocks [112,592) w_hh rows 1920..3839
// ============================================================
#define KBC_BLOCKS 592
__global__ __launch_bounds__(256) void kBC(
    const float* __restrict__ h, const float* __restrict__ attn_b,
    const float* __restrict__ enc, const float* __restrict__ w_hh,
    float* __restrict__ out)
{
    __shared__ __align__(16) float4 svv[512];
    __shared__ float sw[L];
    __shared__ float red[256];
    __shared__ float pr[8];
    int tid = threadIdx.x;

    if (blockIdx.x < 112) {
        float m = -INFINITY;
        for (int i = tid; i < L; i += 256) {
            float v = g_logits[i] + attn_b[i];
            sw[i] = v; m = fmaxf(m, v);
        }
        red[tid] = m; __syncthreads();
        #pragma unroll
        for (int s = 128; s > 0; s >>= 1) { if (tid < s) red[tid] = fmaxf(red[tid], red[tid+s]); __syncthreads(); }
        float mx = red[0]; __syncthreads();

        float sum = 0.f;
        for (int i = tid; i < L; i += 256) { float e = __expf(sw[i] - mx); sw[i] = e; sum += e; }
        red[tid] = sum; __syncthreads();
        #pragma unroll
        for (int s = 128; s > 0; s >>= 1) { if (tid < s) red[tid] += red[tid+s]; __syncthreads(); }
        float inv = 1.f / red[0]; __syncthreads();
        for (int i = tid; i < L; i += 256) sw[i] *= inv;
        __syncthreads();

        if (blockIdx.x == 0)
            for (int i = tid; i < L; i += 256) out[2*H + i] = sw[i];

        int bx = blockIdx.x & 7, by = blockIdx.x >> 3;
        int j  = bx * 256 + tid;
        int r0 = by * 25;
        const float* e = enc + (size_t)r0 * H + j;
        float acc = 0.f;
        #pragma unroll
        for (int i = 0; i < 25; ++i)
            acc += sw[r0 + i] * e[(size_t)i * H];
        atomicAdd(&g_scr[SC_VEC + 2048 + j], acc);
    } else {
        int lane = tid & 31, wid = tid >> 5;
        const float4* h4 = (const float4*)h;
        #pragma unroll
        for (int i = tid; i < 512; i += 256) svv[i] = h4[i];
        __syncthreads();
        int b   = blockIdx.x - 112;               // 0..479
        int row = 1920 + b * 4 + (wid >> 1);      // rows 1920..3839
        int hf  = wid & 1;
        const float4* W = (const float4*)w_hh + (size_t)row * 512 + hf * 256;
        float s = seg_dot8(W, svv + hf * 256, lane);
        s = warp_sum(s);
        if (lane == 0) pr[wid] = s;
        __syncthreads();
        if (tid < 4) g_scr[SC_GH + 1920 + b * 4 + tid] = pr[tid*2] + pr[tid*2+1];
    }
}

// ============================================================
// kD: blocks [0,1024)     comb_W @ [x;ctx] (2 rows/block, warp per quarter)
//     blocks [1024,1600)  w_hh rows 3840..6143 (4 rows/block)
// ============================================================
#define KD_BLOCKS 1600
__global__ __launch_bounds__(256) void kD(
    const float* __restrict__ h,
    const float* __restrict__ comb_W, const float* __restrict__ w_hh)
{
    __shared__ __align__(16) float4 sv[1024];
    __shared__ float pr[8];
    int tid  = threadIdx.x;
    int lane = tid & 31;
    int wid  = tid >> 5;

    if (blockIdx.x < 1024) {
        const float4* gv = (const float4*)(g_scr + SC_VEC);
        #pragma unroll
        for (int i = tid; i < 1024; i += 256) sv[i] = gv[i];
        __syncthreads();
        int row = blockIdx.x * 2 + (wid >> 2);    // 2048 rows
        int q   = wid & 3;
        const float4* W = (const float4*)comb_W + (size_t)row * 1024 + q * 256;
        float s = seg_dot8(W, sv + q * 256, lane);
        s = warp_sum(s);
        if (lane == 0) pr[wid] = s;
        __syncthreads();
        if (tid < 2)
            g_scr[SC_GSUM + blockIdx.x * 2 + tid] =
                pr[tid*4] + pr[tid*4+1] + pr[tid*4+2] + pr[tid*4+3];
    } else {
        const float4* h4 = (const float4*)h;
        #pragma unroll
        for (int i = tid; i < 512; i += 256) sv[i] = h4[i];
        __syncthreads();
        int b   = blockIdx.x - 1024;              // 0..575
        int row = 3840 + b * 4 + (wid >> 1);      // rows 3840..6143
        int hf  = wid & 1;
        const float4* W = (const float4*)w_hh + (size_t)row * 512 + hf * 256;
        float s = seg_dot8(W, sv + hf * 256, lane);
        s = warp_sum(s);
        if (lane == 0) pr[wid] = s;
        __syncthreads();
        if (tid < 4) g_scr[SC_GH + 3840 + b * 4 + tid] = pr[tid*2] + pr[tid*2+1];
    }
}

// ============================================================
// kE: gi = w_ih @ relu(gsum + comb_b) (4 rows/block, warp per half).
// Last block to finish runs the GRU gate epilogue.
// ============================================================
#define KE_BLOCKS 1536
__global__ __launch_bounds__(256) void kE(
    const float* __restrict__ w_ih, const float* __restrict__ comb_b,
    const float* __restrict__ h, const float* __restrict__ b_ih,
    const float* __restrict__ b_hh, float* __restrict__ out)
{
    __shared__ __align__(16) float4 sv[512];
    __shared__ float pr[8];
    __shared__ int is_last;
    int tid  = threadIdx.x;
    int lane = tid & 31;
    int wid  = tid >> 5;

    const float4* gs = (const float4*)(g_scr + SC_GSUM);
    const float4* cb = (const float4*)comb_b;
    #pragma unroll
    for (int i = tid; i < 512; i += 256) {
        float4 gv = gs[i], bv = cb[i];
        sv[i] = make_float4(fmaxf(gv.x + bv.x, 0.f), fmaxf(gv.y + bv.y, 0.f),
                            fmaxf(gv.z + bv.z, 0.f), fmaxf(gv.w + bv.w, 0.f));
    }
    __syncthreads();

    int row = blockIdx.x * 4 + (wid >> 1);        // 6144 rows
    int hf  = wid & 1;
    const float4* W = (const float4*)w_ih + (size_t)row * 512 + hf * 256;
    float s = seg_dot8(W, sv + hf * 256, lane);
    s = warp_sum(s);
    if (lane == 0) pr[wid] = s;
    __syncthreads();
    if (tid < 4) g_scr[SC_GI + blockIdx.x * 4 + tid] = pr[tid*2] + pr[tid*2+1];

    // last-block epilogue
    __syncthreads();
    if (tid == 0) {
        __threadfence();
        int old = atomicAdd(&g_done, 1);
        is_last = (old == KE_BLOCKS - 1);
    }
    __syncthreads();
    if (is_last) {
        if (tid == 0) g_done = 0;      // reset for next graph replay
        __threadfence();
        for (int j = tid; j < H; j += 256) {
            float hr = g_scr[SC_GH + j]       + b_hh[j];
            float hz = g_scr[SC_GH + j + H]   + b_hh[j + H];
            float hn = g_scr[SC_GH + j + 2*H] + b_hh[j + 2*H];
            float ir = g_scr[SC_GI + j]       + b_ih[j]       + hr;
            float iz = g_scr[SC_GI + j + H]   + b_ih[j + H]   + hz;
            float r  = 1.f / (1.f + __expf(-ir));
            float z  = 1.f / (1.f + __expf(-iz));
            float n  = tanhf(g_scr[SC_GI + j + 2*H] + b_ih[j + 2*H] + r * hn);
            float hv = (1.f - z) * n + z * h[j];
            out[j]     = hv;
            out[H + j] = hv;
        }
    }
}

// ============================================================
extern "C" void kernel_launch(void* const* d_in, const int* in_sizes, int n_in,
                              void* d_out, int out_size)
{
    const float* x      = (const float*)d_in[0];
    const float* h      = (const float*)d_in[1];
    const float* enc    = (const float*)d_in[2];
    const float* attn_W = (const float*)d_in[3];
    const float* attn_b = (const float*)d_in[4];
    const float* comb_W = (const float*)d_in[5];
    const float* comb_b = (const float*)d_in[6];
    const float* w_ih   = (const float*)d_in[7];
    const float* w_hh   = (const float*)d_in[8];
    const float* b_ih   = (const float*)d_in[9];
    const float* b_hh   = (const float*)d_in[10];
    float* out = (float*)d_out;

    kA<<<KA_BLOCKS, 256>>>(x, h, attn_W, w_hh);
    kBC<<<KBC_BLOCKS, 256>>>(h, attn_b, enc, w_hh, out);
    kD<<<KD_BLOCKS, 256>>>(h, comb_W, w_hh);
    kE<<<KE_BLOCKS, 256>>>(w_ih, comb_b, h, b_ih, b_hh, out);
}